// round 14
// baseline (speedup 1.0000x reference)
#include <cuda_runtime.h>
#include <cstdint>

#define FULLMASK 0xffffffffu

__device__ float g_step;
__device__ float g_beta[200];

// ---------------------------------------------------------------------------
// Prep kernel (1 block, 64 threads):
//   - computes lambda_max(sigma) via power iteration on S^4 (2 squarings in
//     shared memory, 96 power steps, Rayleigh quotient, 4th root)
//   - writes g_step = 1/lambda_max
//   - thread 0 precomputes the 200 FISTA momentum coefficients (fp32
//     recurrence identical to the reference) into g_beta
// ---------------------------------------------------------------------------
__global__ void prep_kernel(const float* __restrict__ sigma) {
    __shared__ float A[64 * 64];   // starts as S, later holds S^4
    __shared__ float Tm[64 * 64];  // S^2
    __shared__ float v[64];
    __shared__ float red[64];
    const int t = threadIdx.x;     // 64 threads

    for (int idx = t; idx < 4096; idx += 64) A[idx] = sigma[idx];
    __syncthreads();

    // Tm = A * A   (thread t owns column t; A[i*64+k] is a broadcast read,
    // A[k*64+t] is coalesced/conflict-free)
    for (int i = 0; i < 64; ++i) {
        float acc = 0.f;
        for (int k = 0; k < 64; ++k) acc = fmaf(A[i * 64 + k], A[k * 64 + t], acc);
        Tm[i * 64 + t] = acc;
    }
    __syncthreads();
    // A = Tm * Tm  (= S^4)
    for (int i = 0; i < 64; ++i) {
        float acc = 0.f;
        for (int k = 0; k < 64; ++k) acc = fmaf(Tm[i * 64 + k], Tm[k * 64 + t], acc);
        A[i * 64 + t] = acc;
    }
    __syncthreads();

    v[t] = 1.f + 0.01f * (float)t;   // generic start vector
    __syncthreads();

    for (int it = 0; it < 96; ++it) {
        float acc = 0.f;
        for (int i = 0; i < 64; ++i) acc = fmaf(A[i * 64 + t], v[i], acc);
        __syncthreads();
        if ((it & 1) == 1) {  // normalize every 2 steps (lambda(S^4)^2 ~ 6.5e4, safe)
            red[t] = acc * acc;
            __syncthreads();
            for (int s = 32; s > 0; s >>= 1) {
                if (t < s) red[t] += red[t + s];
                __syncthreads();
            }
            acc *= rsqrtf(red[0]);
            __syncthreads();
        }
        v[t] = acc;
        __syncthreads();
    }

    // Rayleigh quotient on S^4: lambda1 = (v^T A v / v^T v)^(1/4)
    float acc = 0.f;
    for (int i = 0; i < 64; ++i) acc = fmaf(A[i * 64 + t], v[i], acc);
    red[t] = acc * v[t];
    __syncthreads();
    for (int s = 32; s > 0; s >>= 1) {
        if (t < s) red[t] += red[t + s];
        __syncthreads();
    }
    float num = red[0];
    __syncthreads();
    red[t] = v[t] * v[t];
    __syncthreads();
    for (int s = 32; s > 0; s >>= 1) {
        if (t < s) red[t] += red[t + s];
        __syncthreads();
    }
    float den = red[0];

    if (t == 0) {
        float lam4 = num / den;
        float lam = sqrtf(sqrtf(lam4));
        g_step = 1.0f / lam;
        // FISTA t-sequence (fp32, matches reference recurrence)
        float tt = 1.f;
        for (int k = 0; k < 200; ++k) {
            float tn = 0.5f * (1.f + sqrtf(1.f + 4.f * tt * tt));
            g_beta[k] = (tt - 1.f) / tn;
            tt = tn;
        }
    }
}

// ---------------------------------------------------------------------------
// Main kernel: one warp solves TWO rows (2 independent FISTA chains for ILP).
// Lane l owns asset indices {l, l+32}. M = I - step*Sigma lives in registers
// as 64 packed f32x2 values (M[i][l], M[i][l+32]). Per inner step:
// one broadcast LDS.64 of (y_i, y_i) + one fma.rn.f32x2 per row.
// Projection: Michelot active-set (exact Euclidean simplex projection).
// ---------------------------------------------------------------------------
__global__ void __launch_bounds__(128, 2) fista_kernel(
    const float* __restrict__ x,
    const float* __restrict__ W1, const float* __restrict__ b1,
    const float* __restrict__ W2, const float* __restrict__ b2,
    const float* __restrict__ W3, const float* __restrict__ b3,
    const float* __restrict__ sigma, const float* __restrict__ gammap,
    float* __restrict__ outw, float* __restrict__ outmu,
    int write_mu, int Brows)
{
    __shared__ unsigned long long ysh[4][2][2][64];  // [warp][buf][row][i]
    const int tid = threadIdx.x;
    const int wp = tid >> 5;
    const int l = tid & 31;

    const int rowA = (blockIdx.x * 4 + wp) * 2;
    if (rowA >= Brows) return;
    const bool haveB = (rowA + 1) < Brows;
    const int rowB = haveB ? (rowA + 1) : rowA;

    const float step = g_step;
    const float gm = gammap[0];

    // ---- MLP prologue: mu = relu(relu(x@W1+b1)@W2+b2)@W3+b3, two rows ----
    float mu0[2], mu1[2];
#pragma unroll
    for (int r = 0; r < 2; ++r) {
        const float* xr = x + (size_t)(r == 0 ? rowA : rowB) * 128;
        float xa = xr[l], xb = xr[l + 32], xc = xr[l + 64], xd = xr[l + 96];
        float h1 = b1[l];
#pragma unroll
        for (int i = 0; i < 32; ++i) h1 = fmaf(__shfl_sync(FULLMASK, xa, i), W1[i * 32 + l], h1);
#pragma unroll
        for (int i = 0; i < 32; ++i) h1 = fmaf(__shfl_sync(FULLMASK, xb, i), W1[(i + 32) * 32 + l], h1);
#pragma unroll
        for (int i = 0; i < 32; ++i) h1 = fmaf(__shfl_sync(FULLMASK, xc, i), W1[(i + 64) * 32 + l], h1);
#pragma unroll
        for (int i = 0; i < 32; ++i) h1 = fmaf(__shfl_sync(FULLMASK, xd, i), W1[(i + 96) * 32 + l], h1);
        h1 = fmaxf(h1, 0.f);

        const int l16 = l & 15;
        float h2 = b2[l16];
#pragma unroll
        for (int i = 0; i < 32; ++i) h2 = fmaf(__shfl_sync(FULLMASK, h1, i), W2[i * 16 + l16], h2);
        h2 = fmaxf(h2, 0.f);

        float m0 = b3[l], m1 = b3[l + 32];
#pragma unroll
        for (int i = 0; i < 16; ++i) {
            float h2i = __shfl_sync(FULLMASK, h2, i);
            m0 = fmaf(h2i, W3[i * 64 + l], m0);
            m1 = fmaf(h2i, W3[i * 64 + l + 32], m1);
        }
        mu0[r] = m0; mu1[r] = m1;
    }

    if (write_mu) {
        outmu[(size_t)rowA * 64 + l] = mu0[0];
        outmu[(size_t)rowA * 64 + l + 32] = mu1[0];
        if (haveB) {
            outmu[(size_t)rowB * 64 + l] = mu0[1];
            outmu[(size_t)rowB * 64 + l + 32] = mu1[1];
        }
    }

    // ---- M = I - step*Sigma, packed pairs in registers ----
    unsigned long long M64[64];
#pragma unroll
    for (int i = 0; i < 64; ++i) {
        float a = ((i == l) ? 1.f : 0.f) - step * sigma[i * 64 + l];
        float b = ((i == l + 32) ? 1.f : 0.f) - step * sigma[i * 64 + l + 32];
        asm("mov.b64 %0, {%1, %2};" : "=l"(M64[i]) : "f"(a), "f"(b));
    }

    // q = -step*p = step*gamma*mu  (so v = y@M + q == y - step*(y@Sigma + p))
    const float sg = step * gm;
    unsigned long long qA, qB;
    {
        float a = sg * mu0[0], b = sg * mu1[0];
        asm("mov.b64 %0, {%1, %2};" : "=l"(qA) : "f"(a), "f"(b));
        float c = sg * mu0[1], d = sg * mu1[1];
        asm("mov.b64 %0, {%1, %2};" : "=l"(qB) : "f"(c), "f"(d));
    }

    const float winit = 1.f / 64.f;
    float wA0 = winit, wA1 = winit, wB0 = winit, wB1 = winit;
    float yA0 = winit, yA1 = winit, yB0 = winit, yB1 = winit;
    const unsigned long long ZPK = 0ull;

    for (int k = 0; k < 200; ++k) {
        const int buf = k & 1;
        unsigned long long p;
        asm("mov.b64 %0, {%1, %1};" : "=l"(p) : "f"(yA0)); ysh[wp][buf][0][l] = p;
        asm("mov.b64 %0, {%1, %1};" : "=l"(p) : "f"(yA1)); ysh[wp][buf][0][l + 32] = p;
        asm("mov.b64 %0, {%1, %1};" : "=l"(p) : "f"(yB0)); ysh[wp][buf][1][l] = p;
        asm("mov.b64 %0, {%1, %1};" : "=l"(p) : "f"(yB1)); ysh[wp][buf][1][l + 32] = p;
        __syncwarp();

        // v = y @ M + q  (4 independent f32x2 accumulator chains)
        unsigned long long vA0p = qA, vA1p = ZPK, vB0p = qB, vB1p = ZPK;
        const unsigned long long* ya = ysh[wp][buf][0];
        const unsigned long long* yb = ysh[wp][buf][1];
#pragma unroll
        for (int i = 0; i < 64; i += 2) {
            asm("fma.rn.f32x2 %0, %1, %2, %0;" : "+l"(vA0p) : "l"(M64[i]),     "l"(ya[i]));
            asm("fma.rn.f32x2 %0, %1, %2, %0;" : "+l"(vB0p) : "l"(M64[i]),     "l"(yb[i]));
            asm("fma.rn.f32x2 %0, %1, %2, %0;" : "+l"(vA1p) : "l"(M64[i + 1]), "l"(ya[i + 1]));
            asm("fma.rn.f32x2 %0, %1, %2, %0;" : "+l"(vB1p) : "l"(M64[i + 1]), "l"(yb[i + 1]));
        }
        unsigned long long vA, vB;
        asm("add.rn.f32x2 %0, %1, %2;" : "=l"(vA) : "l"(vA0p), "l"(vA1p));
        asm("add.rn.f32x2 %0, %1, %2;" : "=l"(vB) : "l"(vB0p), "l"(vB1p));
        float vA0, vA1, vB0, vB1;
        asm("mov.b64 {%0, %1}, %2;" : "=f"(vA0), "=f"(vA1) : "l"(vA));
        asm("mov.b64 {%0, %1}, %2;" : "=f"(vB0), "=f"(vB1) : "l"(vB));

        // ---- simplex projection (Michelot, dual-row) ----
        float sA = vA0 + vA1, sB = vB0 + vB1;
#pragma unroll
        for (int o = 16; o > 0; o >>= 1) {
            sA += __shfl_xor_sync(FULLMASK, sA, o);
            sB += __shfl_xor_sync(FULLMASK, sB, o);
        }
        float thA = (sA - 1.f) * 0.015625f;   // all 64 active
        float thB = (sB - 1.f) * 0.015625f;
        int cpA = 64, cpB = 64;
        bool dA = false, dB = false;
        for (int pass = 0; pass < 64; ++pass) {
            bool aA0 = vA0 > thA, aA1 = vA1 > thA;
            bool aB0 = vB0 > thB, aB1 = vB1 > thB;
            int cA = __popc(__ballot_sync(FULLMASK, aA0)) + __popc(__ballot_sync(FULLMASK, aA1));
            int cB = __popc(__ballot_sync(FULLMASK, aB0)) + __popc(__ballot_sync(FULLMASK, aB1));
            float slA = (aA0 ? vA0 : 0.f) + (aA1 ? vA1 : 0.f);
            float slB = (aB0 ? vB0 : 0.f) + (aB1 ? vB1 : 0.f);
#pragma unroll
            for (int o = 16; o > 0; o >>= 1) {
                slA += __shfl_xor_sync(FULLMASK, slA, o);
                slB += __shfl_xor_sync(FULLMASK, slB, o);
            }
            dA = dA || (cA == cpA);
            dB = dB || (cB == cpB);
            if (dA && dB) break;
            if (!dA) { thA = __fdividef(slA - 1.f, (float)cA); cpA = cA; }
            if (!dB) { thB = __fdividef(slB - 1.f, (float)cB); cpB = cB; }
        }
        float wnA0 = fmaxf(vA0 - thA, 0.f), wnA1 = fmaxf(vA1 - thA, 0.f);
        float wnB0 = fmaxf(vB0 - thB, 0.f), wnB1 = fmaxf(vB1 - thB, 0.f);

        // ---- momentum ----
        const float beta = g_beta[k];
        yA0 = fmaf(beta, wnA0 - wA0, wnA0);
        yA1 = fmaf(beta, wnA1 - wA1, wnA1);
        yB0 = fmaf(beta, wnB0 - wB0, wnB0);
        yB1 = fmaf(beta, wnB1 - wB1, wnB1);
        wA0 = wnA0; wA1 = wnA1; wB0 = wnB0; wB1 = wnB1;
    }

    outw[(size_t)rowA * 64 + l] = wA0;
    outw[(size_t)rowA * 64 + l + 32] = wA1;
    if (haveB) {
        outw[(size_t)rowB * 64 + l] = wB0;
        outw[(size_t)rowB * 64 + l + 32] = wB1;
    }
}

// ---------------------------------------------------------------------------
extern "C" void kernel_launch(void* const* d_in, const int* in_sizes, int n_in,
                              void* d_out, int out_size) {
    const float* x     = (const float*)d_in[0];
    const float* W1    = (const float*)d_in[1];
    const float* b1    = (const float*)d_in[2];
    const float* W2    = (const float*)d_in[3];
    const float* b2    = (const float*)d_in[4];
    const float* W3    = (const float*)d_in[5];
    const float* b3    = (const float*)d_in[6];
    const float* sigma = (const float*)d_in[7];
    const float* gamma = (const float*)d_in[8];
    float* out = (float*)d_out;

    const int Brows = in_sizes[0] / 128;             // 16384
    const int write_mu = (out_size >= Brows * 128) ? 1 : 0;  // tuple (weights, mu)

    prep_kernel<<<1, 64>>>(sigma);

    const int rows_per_block = 8;                    // 4 warps x 2 rows
    const int grid = (Brows + rows_per_block - 1) / rows_per_block;
    fista_kernel<<<grid, 128>>>(x, W1, b1, W2, b2, W3, b3, sigma, gamma,
                                out, out + (size_t)Brows * 64, write_mu, Brows);
}

// round 15
// speedup vs baseline: 1.0860x; 1.0860x over previous
#include <cuda_runtime.h>
#include <cstdint>

#define FULLMASK 0xffffffffu

__device__ float g_step;
__device__ float g_beta[200];

// ---------------------------------------------------------------------------
// Prep kernel (1 block, 64 threads): lambda_max(sigma) via power iteration on
// S^4 (2 shared-memory squarings, 96 power steps, Rayleigh quotient, 4th
// root) -> g_step = 1/lambda_max. Thread 0 also precomputes the 200 FISTA
// momentum coefficients (fp32 recurrence identical to the reference).
// ---------------------------------------------------------------------------
__global__ void prep_kernel(const float* __restrict__ sigma) {
    __shared__ float A[64 * 64];
    __shared__ float Tm[64 * 64];
    __shared__ float v[64];
    __shared__ float red[64];
    const int t = threadIdx.x;

    for (int idx = t; idx < 4096; idx += 64) A[idx] = sigma[idx];
    __syncthreads();

    for (int i = 0; i < 64; ++i) {
        float acc = 0.f;
        for (int k = 0; k < 64; ++k) acc = fmaf(A[i * 64 + k], A[k * 64 + t], acc);
        Tm[i * 64 + t] = acc;
    }
    __syncthreads();
    for (int i = 0; i < 64; ++i) {
        float acc = 0.f;
        for (int k = 0; k < 64; ++k) acc = fmaf(Tm[i * 64 + k], Tm[k * 64 + t], acc);
        A[i * 64 + t] = acc;
    }
    __syncthreads();

    v[t] = 1.f + 0.01f * (float)t;
    __syncthreads();

    for (int it = 0; it < 96; ++it) {
        float acc = 0.f;
        for (int i = 0; i < 64; ++i) acc = fmaf(A[i * 64 + t], v[i], acc);
        __syncthreads();
        if ((it & 1) == 1) {
            red[t] = acc * acc;
            __syncthreads();
            for (int s = 32; s > 0; s >>= 1) {
                if (t < s) red[t] += red[t + s];
                __syncthreads();
            }
            acc *= rsqrtf(red[0]);
            __syncthreads();
        }
        v[t] = acc;
        __syncthreads();
    }

    float acc = 0.f;
    for (int i = 0; i < 64; ++i) acc = fmaf(A[i * 64 + t], v[i], acc);
    red[t] = acc * v[t];
    __syncthreads();
    for (int s = 32; s > 0; s >>= 1) {
        if (t < s) red[t] += red[t + s];
        __syncthreads();
    }
    float num = red[0];
    __syncthreads();
    red[t] = v[t] * v[t];
    __syncthreads();
    for (int s = 32; s > 0; s >>= 1) {
        if (t < s) red[t] += red[t + s];
        __syncthreads();
    }
    float den = red[0];

    if (t == 0) {
        float lam = sqrtf(sqrtf(num / den));
        g_step = 1.0f / lam;
        float tt = 1.f;
        for (int k = 0; k < 200; ++k) {
            float tn = 0.5f * (1.f + sqrtf(1.f + 4.f * tt * tt));
            g_beta[k] = (tt - 1.f) / tn;
            tt = tn;
        }
    }
}

// ---------------------------------------------------------------------------
// Main kernel: one warp solves TWO rows. M = I - step*Sigma lives in SHARED
// memory (16KB, shared by all 4 warps of the block) as packed f32x2 pairs
// (M[i][l], M[i][l+32]); y broadcasts are packed so both rows come from one
// LDS.128. Inner step: 1 LDS.128 + 1 LDS.64 + 2 fma.rn.f32x2 for 2 rows.
// Projection: Michelot active-set (exact). Early exit on bitwise-stationary
// state (provably identical output to running all 200 iterations).
// ---------------------------------------------------------------------------
__global__ void __launch_bounds__(128, 5) fista_kernel(
    const float* __restrict__ x,
    const float* __restrict__ W1, const float* __restrict__ b1,
    const float* __restrict__ W2, const float* __restrict__ b2,
    const float* __restrict__ W3, const float* __restrict__ b3,
    const float* __restrict__ sigma, const float* __restrict__ gammap,
    float* __restrict__ outw, float* __restrict__ outmu,
    int write_mu, int Brows)
{
    __shared__ unsigned long long Msh[64][32];     // 16 KB, block-shared
    __shared__ ulonglong2 ysh[4][2][64];           // 8 KB: [warp][buf][i] = {yA_i pair, yB_i pair}
    __shared__ float bsh[200];

    const int tid = threadIdx.x;
    const int wp = tid >> 5;
    const int l = tid & 31;

    const float step = g_step;

    // Block-cooperative: M = I - step*Sigma, packed pairs in shared
    for (int i = wp; i < 64; i += 4) {
        float a = ((i == l) ? 1.f : 0.f) - step * sigma[i * 64 + l];
        float b = ((i == l + 32) ? 1.f : 0.f) - step * sigma[i * 64 + l + 32];
        unsigned long long m;
        asm("mov.b64 %0, {%1, %2};" : "=l"(m) : "f"(a), "f"(b));
        Msh[i][l] = m;
    }
    for (int k = tid; k < 200; k += 128) bsh[k] = g_beta[k];
    __syncthreads();

    const int rowA = (blockIdx.x * 4 + wp) * 2;
    if (rowA >= Brows) return;
    const bool haveB = (rowA + 1) < Brows;
    const int rowB = haveB ? (rowA + 1) : rowA;
    const float gm = gammap[0];

    // ---- MLP prologue: mu = relu(relu(x@W1+b1)@W2+b2)@W3+b3, two rows ----
    float mu0[2], mu1[2];
#pragma unroll
    for (int r = 0; r < 2; ++r) {
        const float* xr = x + (size_t)(r == 0 ? rowA : rowB) * 128;
        float xa = xr[l], xb = xr[l + 32], xc = xr[l + 64], xd = xr[l + 96];
        float h1 = b1[l];
#pragma unroll
        for (int i = 0; i < 32; ++i) h1 = fmaf(__shfl_sync(FULLMASK, xa, i), W1[i * 32 + l], h1);
#pragma unroll
        for (int i = 0; i < 32; ++i) h1 = fmaf(__shfl_sync(FULLMASK, xb, i), W1[(i + 32) * 32 + l], h1);
#pragma unroll
        for (int i = 0; i < 32; ++i) h1 = fmaf(__shfl_sync(FULLMASK, xc, i), W1[(i + 64) * 32 + l], h1);
#pragma unroll
        for (int i = 0; i < 32; ++i) h1 = fmaf(__shfl_sync(FULLMASK, xd, i), W1[(i + 96) * 32 + l], h1);
        h1 = fmaxf(h1, 0.f);

        const int l16 = l & 15;
        float h2 = b2[l16];
#pragma unroll
        for (int i = 0; i < 32; ++i) h2 = fmaf(__shfl_sync(FULLMASK, h1, i), W2[i * 16 + l16], h2);
        h2 = fmaxf(h2, 0.f);

        float m0 = b3[l], m1 = b3[l + 32];
#pragma unroll
        for (int i = 0; i < 16; ++i) {
            float h2i = __shfl_sync(FULLMASK, h2, i);
            m0 = fmaf(h2i, W3[i * 64 + l], m0);
            m1 = fmaf(h2i, W3[i * 64 + l + 32], m1);
        }
        mu0[r] = m0; mu1[r] = m1;
    }

    if (write_mu) {
        outmu[(size_t)rowA * 64 + l] = mu0[0];
        outmu[(size_t)rowA * 64 + l + 32] = mu1[0];
        if (haveB) {
            outmu[(size_t)rowB * 64 + l] = mu0[1];
            outmu[(size_t)rowB * 64 + l + 32] = mu1[1];
        }
    }

    // q = step*gamma*mu, packed  (v = y@M + q == y - step*(y@Sigma + p))
    const float sg = step * gm;
    unsigned long long qA, qB;
    {
        float a = sg * mu0[0], b = sg * mu1[0];
        asm("mov.b64 %0, {%1, %2};" : "=l"(qA) : "f"(a), "f"(b));
        float c = sg * mu0[1], d = sg * mu1[1];
        asm("mov.b64 %0, {%1, %2};" : "=l"(qB) : "f"(c), "f"(d));
    }

    const float winit = 1.f / 64.f;
    float wA0 = winit, wA1 = winit, wB0 = winit, wB1 = winit;
    float yA0 = winit, yA1 = winit, yB0 = winit, yB1 = winit;

    for (int k = 0; k < 200; ++k) {
        const int buf = k & 1;
        // write y broadcasts: entry i holds {(yA_i,yA_i),(yB_i,yB_i)}
        {
            ulonglong2 e;
            asm("mov.b64 %0, {%1, %1};" : "=l"(e.x) : "f"(yA0));
            asm("mov.b64 %0, {%1, %1};" : "=l"(e.y) : "f"(yB0));
            ysh[wp][buf][l] = e;
            asm("mov.b64 %0, {%1, %1};" : "=l"(e.x) : "f"(yA1));
            asm("mov.b64 %0, {%1, %1};" : "=l"(e.y) : "f"(yB1));
            ysh[wp][buf][l + 32] = e;
        }
        __syncwarp();

        // v = y @ M + q : per i, 1 LDS.128 (both rows' y) + 1 LDS.64 (M) + 2 fma.f32x2
        unsigned long long vA0p = qA, vA1p = 0ull, vB0p = qB, vB1p = 0ull;
        const ulonglong2* Y = ysh[wp][buf];
#pragma unroll
        for (int i = 0; i < 64; i += 2) {
            ulonglong2 y0 = Y[i];
            ulonglong2 y1 = Y[i + 1];
            unsigned long long m0 = Msh[i][l];
            unsigned long long m1 = Msh[i + 1][l];
            asm("fma.rn.f32x2 %0, %1, %2, %0;" : "+l"(vA0p) : "l"(m0), "l"(y0.x));
            asm("fma.rn.f32x2 %0, %1, %2, %0;" : "+l"(vB0p) : "l"(m0), "l"(y0.y));
            asm("fma.rn.f32x2 %0, %1, %2, %0;" : "+l"(vA1p) : "l"(m1), "l"(y1.x));
            asm("fma.rn.f32x2 %0, %1, %2, %0;" : "+l"(vB1p) : "l"(m1), "l"(y1.y));
        }
        unsigned long long vA, vB;
        asm("add.rn.f32x2 %0, %1, %2;" : "=l"(vA) : "l"(vA0p), "l"(vA1p));
        asm("add.rn.f32x2 %0, %1, %2;" : "=l"(vB) : "l"(vB0p), "l"(vB1p));
        float vA0, vA1, vB0, vB1;
        asm("mov.b64 {%0, %1}, %2;" : "=f"(vA0), "=f"(vA1) : "l"(vA));
        asm("mov.b64 {%0, %1}, %2;" : "=f"(vB0), "=f"(vB1) : "l"(vB));

        // ---- simplex projection (Michelot, dual-row) ----
        float sA = vA0 + vA1, sB = vB0 + vB1;
#pragma unroll
        for (int o = 16; o > 0; o >>= 1) {
            sA += __shfl_xor_sync(FULLMASK, sA, o);
            sB += __shfl_xor_sync(FULLMASK, sB, o);
        }
        float thA = (sA - 1.f) * 0.015625f;
        float thB = (sB - 1.f) * 0.015625f;
        int cpA = 64, cpB = 64;
        bool dA = false, dB = false;
        for (int pass = 0; pass < 64; ++pass) {
            bool aA0 = vA0 > thA, aA1 = vA1 > thA;
            bool aB0 = vB0 > thB, aB1 = vB1 > thB;
            int cA = __popc(__ballot_sync(FULLMASK, aA0)) + __popc(__ballot_sync(FULLMASK, aA1));
            int cB = __popc(__ballot_sync(FULLMASK, aB0)) + __popc(__ballot_sync(FULLMASK, aB1));
            float slA = (aA0 ? vA0 : 0.f) + (aA1 ? vA1 : 0.f);
            float slB = (aB0 ? vB0 : 0.f) + (aB1 ? vB1 : 0.f);
#pragma unroll
            for (int o = 16; o > 0; o >>= 1) {
                slA += __shfl_xor_sync(FULLMASK, slA, o);
                slB += __shfl_xor_sync(FULLMASK, slB, o);
            }
            dA = dA || (cA == cpA);
            dB = dB || (cB == cpB);
            if (dA && dB) break;
            if (!dA) { thA = __fdividef(slA - 1.f, (float)cA); cpA = cA; }
            if (!dB) { thB = __fdividef(slB - 1.f, (float)cB); cpB = cB; }
        }
        float wnA0 = fmaxf(vA0 - thA, 0.f), wnA1 = fmaxf(vA1 - thA, 0.f);
        float wnB0 = fmaxf(vB0 - thB, 0.f), wnB1 = fmaxf(vB1 - thB, 0.f);

        // ---- momentum ----
        const float beta = bsh[k];
        float nyA0 = fmaf(beta, wnA0 - wA0, wnA0);
        float nyA1 = fmaf(beta, wnA1 - wA1, wnA1);
        float nyB0 = fmaf(beta, wnB0 - wB0, wnB0);
        float nyB1 = fmaf(beta, wnB1 - wB1, wnB1);

        // ---- exact early exit: state bitwise stationary => all remaining
        // iterations are identity (w_new==w forces y_new==w_new, beta-free) ----
        bool stA = (wnA0 == wA0) & (wnA1 == wA1) & (nyA0 == yA0) & (nyA1 == yA1);
        bool stB = (wnB0 == wB0) & (wnB1 == wB1) & (nyB0 == yB0) & (nyB1 == yB1);
        bool doneA = __all_sync(FULLMASK, stA);
        bool doneB = __all_sync(FULLMASK, stB);

        wA0 = wnA0; wA1 = wnA1; wB0 = wnB0; wB1 = wnB1;
        yA0 = nyA0; yA1 = nyA1; yB0 = nyB0; yB1 = nyB1;

        if (doneA && doneB) break;
    }

    outw[(size_t)rowA * 64 + l] = wA0;
    outw[(size_t)rowA * 64 + l + 32] = wA1;
    if (haveB) {
        outw[(size_t)rowB * 64 + l] = wB0;
        outw[(size_t)rowB * 64 + l + 32] = wB1;
    }
}

// ---------------------------------------------------------------------------
extern "C" void kernel_launch(void* const* d_in, const int* in_sizes, int n_in,
                              void* d_out, int out_size) {
    const float* x     = (const float*)d_in[0];
    const float* W1    = (const float*)d_in[1];
    const float* b1    = (const float*)d_in[2];
    const float* W2    = (const float*)d_in[3];
    const float* b2    = (const float*)d_in[4];
    const float* W3    = (const float*)d_in[5];
    const float* b3    = (const float*)d_in[6];
    const float* sigma = (const float*)d_in[7];
    const float* gamma = (const float*)d_in[8];
    float* out = (float*)d_out;

    const int Brows = in_sizes[0] / 128;                     // 16384
    const int write_mu = (out_size >= Brows * 128) ? 1 : 0;  // tuple (weights, mu)

    prep_kernel<<<1, 64>>>(sigma);

    const int rows_per_block = 8;  // 4 warps x 2 rows
    const int grid = (Brows + rows_per_block - 1) / rows_per_block;
    fista_kernel<<<grid, 128>>>(x, W1, b1, W2, b2, W3, b3, sigma, gamma,
                                out, out + (size_t)Brows * 64, write_mu, Brows);
}

// round 16
// speedup vs baseline: 1.0867x; 1.0007x over previous
#include <cuda_runtime.h>
#include <cstdint>

#define FULLMASK 0xffffffffu

__device__ float g_step;
__device__ float g_beta[200];

// ---------------------------------------------------------------------------
// Prep kernel (1 block, 64 threads): lambda_max(sigma) via power iteration on
// S^4 (2 shared-memory squarings, 96 power steps, Rayleigh quotient, 4th
// root) -> g_step = 1/lambda_max. Thread 0 also precomputes the 200 FISTA
// momentum coefficients (fp32 recurrence identical to the reference).
// ---------------------------------------------------------------------------
__global__ void prep_kernel(const float* __restrict__ sigma) {
    __shared__ float A[64 * 64];
    __shared__ float Tm[64 * 64];
    __shared__ float v[64];
    __shared__ float red[64];
    const int t = threadIdx.x;

    for (int idx = t; idx < 4096; idx += 64) A[idx] = sigma[idx];
    __syncthreads();

    for (int i = 0; i < 64; ++i) {
        float acc = 0.f;
        for (int k = 0; k < 64; ++k) acc = fmaf(A[i * 64 + k], A[k * 64 + t], acc);
        Tm[i * 64 + t] = acc;
    }
    __syncthreads();
    for (int i = 0; i < 64; ++i) {
        float acc = 0.f;
        for (int k = 0; k < 64; ++k) acc = fmaf(Tm[i * 64 + k], Tm[k * 64 + t], acc);
        A[i * 64 + t] = acc;
    }
    __syncthreads();

    v[t] = 1.f + 0.01f * (float)t;
    __syncthreads();

    for (int it = 0; it < 96; ++it) {
        float acc = 0.f;
        for (int i = 0; i < 64; ++i) acc = fmaf(A[i * 64 + t], v[i], acc);
        __syncthreads();
        if ((it & 1) == 1) {
            red[t] = acc * acc;
            __syncthreads();
            for (int s = 32; s > 0; s >>= 1) {
                if (t < s) red[t] += red[t + s];
                __syncthreads();
            }
            acc *= rsqrtf(red[0]);
            __syncthreads();
        }
        v[t] = acc;
        __syncthreads();
    }

    float acc = 0.f;
    for (int i = 0; i < 64; ++i) acc = fmaf(A[i * 64 + t], v[i], acc);
    red[t] = acc * v[t];
    __syncthreads();
    for (int s = 32; s > 0; s >>= 1) {
        if (t < s) red[t] += red[t + s];
        __syncthreads();
    }
    float num = red[0];
    __syncthreads();
    red[t] = v[t] * v[t];
    __syncthreads();
    for (int s = 32; s > 0; s >>= 1) {
        if (t < s) red[t] += red[t + s];
        __syncthreads();
    }
    float den = red[0];

    if (t == 0) {
        float lam = sqrtf(sqrtf(num / den));
        g_step = 1.0f / lam;
        float tt = 1.f;
        for (int k = 0; k < 200; ++k) {
            float tn = 0.5f * (1.f + sqrtf(1.f + 4.f * tt * tt));
            g_beta[k] = (tt - 1.f) / tn;
            tt = tn;
        }
    }
}

// ---------------------------------------------------------------------------
// Main kernel: one warp solves TWO rows. M = I - step*Sigma lives in SHARED
// memory (16KB, shared by all 4 warps of the block) as packed f32x2 pairs
// (M[i][l], M[i][l+32]); y broadcasts are packed so both rows come from one
// LDS.128. Inner step: 1 LDS.128 + 1 LDS.64 + 2 fma.rn.f32x2 for 2 rows.
// Projection: Michelot active-set (exact). Early exit on bitwise-stationary
// state (provably identical output to running all 200 iterations).
// ---------------------------------------------------------------------------
__global__ void __launch_bounds__(128, 5) fista_kernel(
    const float* __restrict__ x,
    const float* __restrict__ W1, const float* __restrict__ b1,
    const float* __restrict__ W2, const float* __restrict__ b2,
    const float* __restrict__ W3, const float* __restrict__ b3,
    const float* __restrict__ sigma, const float* __restrict__ gammap,
    float* __restrict__ outw, float* __restrict__ outmu,
    int write_mu, int Brows)
{
    __shared__ unsigned long long Msh[64][32];     // 16 KB, block-shared
    __shared__ ulonglong2 ysh[4][2][64];           // 8 KB: [warp][buf][i] = {yA_i pair, yB_i pair}
    __shared__ float bsh[200];

    const int tid = threadIdx.x;
    const int wp = tid >> 5;
    const int l = tid & 31;

    const float step = g_step;

    // Block-cooperative: M = I - step*Sigma, packed pairs in shared
    for (int i = wp; i < 64; i += 4) {
        float a = ((i == l) ? 1.f : 0.f) - step * sigma[i * 64 + l];
        float b = ((i == l + 32) ? 1.f : 0.f) - step * sigma[i * 64 + l + 32];
        unsigned long long m;
        asm("mov.b64 %0, {%1, %2};" : "=l"(m) : "f"(a), "f"(b));
        Msh[i][l] = m;
    }
    for (int k = tid; k < 200; k += 128) bsh[k] = g_beta[k];
    __syncthreads();

    const int rowA = (blockIdx.x * 4 + wp) * 2;
    if (rowA >= Brows) return;
    const bool haveB = (rowA + 1) < Brows;
    const int rowB = haveB ? (rowA + 1) : rowA;
    const float gm = gammap[0];

    // ---- MLP prologue: mu = relu(relu(x@W1+b1)@W2+b2)@W3+b3, two rows ----
    float mu0[2], mu1[2];
#pragma unroll
    for (int r = 0; r < 2; ++r) {
        const float* xr = x + (size_t)(r == 0 ? rowA : rowB) * 128;
        float xa = xr[l], xb = xr[l + 32], xc = xr[l + 64], xd = xr[l + 96];
        float h1 = b1[l];
#pragma unroll
        for (int i = 0; i < 32; ++i) h1 = fmaf(__shfl_sync(FULLMASK, xa, i), W1[i * 32 + l], h1);
#pragma unroll
        for (int i = 0; i < 32; ++i) h1 = fmaf(__shfl_sync(FULLMASK, xb, i), W1[(i + 32) * 32 + l], h1);
#pragma unroll
        for (int i = 0; i < 32; ++i) h1 = fmaf(__shfl_sync(FULLMASK, xc, i), W1[(i + 64) * 32 + l], h1);
#pragma unroll
        for (int i = 0; i < 32; ++i) h1 = fmaf(__shfl_sync(FULLMASK, xd, i), W1[(i + 96) * 32 + l], h1);
        h1 = fmaxf(h1, 0.f);

        const int l16 = l & 15;
        float h2 = b2[l16];
#pragma unroll
        for (int i = 0; i < 32; ++i) h2 = fmaf(__shfl_sync(FULLMASK, h1, i), W2[i * 16 + l16], h2);
        h2 = fmaxf(h2, 0.f);

        float m0 = b3[l], m1 = b3[l + 32];
#pragma unroll
        for (int i = 0; i < 16; ++i) {
            float h2i = __shfl_sync(FULLMASK, h2, i);
            m0 = fmaf(h2i, W3[i * 64 + l], m0);
            m1 = fmaf(h2i, W3[i * 64 + l + 32], m1);
        }
        mu0[r] = m0; mu1[r] = m1;
    }

    if (write_mu) {
        outmu[(size_t)rowA * 64 + l] = mu0[0];
        outmu[(size_t)rowA * 64 + l + 32] = mu1[0];
        if (haveB) {
            outmu[(size_t)rowB * 64 + l] = mu0[1];
            outmu[(size_t)rowB * 64 + l + 32] = mu1[1];
        }
    }

    // q = step*gamma*mu, packed  (v = y@M + q == y - step*(y@Sigma + p))
    const float sg = step * gm;
    unsigned long long qA, qB;
    {
        float a = sg * mu0[0], b = sg * mu1[0];
        asm("mov.b64 %0, {%1, %2};" : "=l"(qA) : "f"(a), "f"(b));
        float c = sg * mu0[1], d = sg * mu1[1];
        asm("mov.b64 %0, {%1, %2};" : "=l"(qB) : "f"(c), "f"(d));
    }

    const float winit = 1.f / 64.f;
    float wA0 = winit, wA1 = winit, wB0 = winit, wB1 = winit;
    float yA0 = winit, yA1 = winit, yB0 = winit, yB1 = winit;

    for (int k = 0; k < 200; ++k) {
        const int buf = k & 1;
        // write y broadcasts: entry i holds {(yA_i,yA_i),(yB_i,yB_i)}
        {
            ulonglong2 e;
            asm("mov.b64 %0, {%1, %1};" : "=l"(e.x) : "f"(yA0));
            asm("mov.b64 %0, {%1, %1};" : "=l"(e.y) : "f"(yB0));
            ysh[wp][buf][l] = e;
            asm("mov.b64 %0, {%1, %1};" : "=l"(e.x) : "f"(yA1));
            asm("mov.b64 %0, {%1, %1};" : "=l"(e.y) : "f"(yB1));
            ysh[wp][buf][l + 32] = e;
        }
        __syncwarp();

        // v = y @ M + q : per i, 1 LDS.128 (both rows' y) + 1 LDS.64 (M) + 2 fma.f32x2
        unsigned long long vA0p = qA, vA1p = 0ull, vB0p = qB, vB1p = 0ull;
        const ulonglong2* Y = ysh[wp][buf];
#pragma unroll
        for (int i = 0; i < 64; i += 2) {
            ulonglong2 y0 = Y[i];
            ulonglong2 y1 = Y[i + 1];
            unsigned long long m0 = Msh[i][l];
            unsigned long long m1 = Msh[i + 1][l];
            asm("fma.rn.f32x2 %0, %1, %2, %0;" : "+l"(vA0p) : "l"(m0), "l"(y0.x));
            asm("fma.rn.f32x2 %0, %1, %2, %0;" : "+l"(vB0p) : "l"(m0), "l"(y0.y));
            asm("fma.rn.f32x2 %0, %1, %2, %0;" : "+l"(vA1p) : "l"(m1), "l"(y1.x));
            asm("fma.rn.f32x2 %0, %1, %2, %0;" : "+l"(vB1p) : "l"(m1), "l"(y1.y));
        }
        unsigned long long vA, vB;
        asm("add.rn.f32x2 %0, %1, %2;" : "=l"(vA) : "l"(vA0p), "l"(vA1p));
        asm("add.rn.f32x2 %0, %1, %2;" : "=l"(vB) : "l"(vB0p), "l"(vB1p));
        float vA0, vA1, vB0, vB1;
        asm("mov.b64 {%0, %1}, %2;" : "=f"(vA0), "=f"(vA1) : "l"(vA));
        asm("mov.b64 {%0, %1}, %2;" : "=f"(vB0), "=f"(vB1) : "l"(vB));

        // ---- simplex projection (Michelot, dual-row) ----
        float sA = vA0 + vA1, sB = vB0 + vB1;
#pragma unroll
        for (int o = 16; o > 0; o >>= 1) {
            sA += __shfl_xor_sync(FULLMASK, sA, o);
            sB += __shfl_xor_sync(FULLMASK, sB, o);
        }
        float thA = (sA - 1.f) * 0.015625f;
        float thB = (sB - 1.f) * 0.015625f;
        int cpA = 64, cpB = 64;
        bool dA = false, dB = false;
        for (int pass = 0; pass < 64; ++pass) {
            bool aA0 = vA0 > thA, aA1 = vA1 > thA;
            bool aB0 = vB0 > thB, aB1 = vB1 > thB;
            int cA = __popc(__ballot_sync(FULLMASK, aA0)) + __popc(__ballot_sync(FULLMASK, aA1));
            int cB = __popc(__ballot_sync(FULLMASK, aB0)) + __popc(__ballot_sync(FULLMASK, aB1));
            float slA = (aA0 ? vA0 : 0.f) + (aA1 ? vA1 : 0.f);
            float slB = (aB0 ? vB0 : 0.f) + (aB1 ? vB1 : 0.f);
#pragma unroll
            for (int o = 16; o > 0; o >>= 1) {
                slA += __shfl_xor_sync(FULLMASK, slA, o);
                slB += __shfl_xor_sync(FULLMASK, slB, o);
            }
            dA = dA || (cA == cpA);
            dB = dB || (cB == cpB);
            if (dA && dB) break;
            if (!dA) { thA = __fdividef(slA - 1.f, (float)cA); cpA = cA; }
            if (!dB) { thB = __fdividef(slB - 1.f, (float)cB); cpB = cB; }
        }
        float wnA0 = fmaxf(vA0 - thA, 0.f), wnA1 = fmaxf(vA1 - thA, 0.f);
        float wnB0 = fmaxf(vB0 - thB, 0.f), wnB1 = fmaxf(vB1 - thB, 0.f);

        // ---- momentum ----
        const float beta = bsh[k];
        float nyA0 = fmaf(beta, wnA0 - wA0, wnA0);
        float nyA1 = fmaf(beta, wnA1 - wA1, wnA1);
        float nyB0 = fmaf(beta, wnB0 - wB0, wnB0);
        float nyB1 = fmaf(beta, wnB1 - wB1, wnB1);

        // ---- exact early exit: state bitwise stationary => all remaining
        // iterations are identity (w_new==w forces y_new==w_new, beta-free) ----
        bool stA = (wnA0 == wA0) & (wnA1 == wA1) & (nyA0 == yA0) & (nyA1 == yA1);
        bool stB = (wnB0 == wB0) & (wnB1 == wB1) & (nyB0 == yB0) & (nyB1 == yB1);
        bool doneA = __all_sync(FULLMASK, stA);
        bool doneB = __all_sync(FULLMASK, stB);

        wA0 = wnA0; wA1 = wnA1; wB0 = wnB0; wB1 = wnB1;
        yA0 = nyA0; yA1 = nyA1; yB0 = nyB0; yB1 = nyB1;

        if (doneA && doneB) break;
    }

    outw[(size_t)rowA * 64 + l] = wA0;
    outw[(size_t)rowA * 64 + l + 32] = wA1;
    if (haveB) {
        outw[(size_t)rowB * 64 + l] = wB0;
        outw[(size_t)rowB * 64 + l + 32] = wB1;
    }
}

// ---------------------------------------------------------------------------
extern "C" void kernel_launch(void* const* d_in, const int* in_sizes, int n_in,
                              void* d_out, int out_size) {
    const float* x     = (const float*)d_in[0];
    const float* W1    = (const float*)d_in[1];
    const float* b1    = (const float*)d_in[2];
    const float* W2    = (const float*)d_in[3];
    const float* b2    = (const float*)d_in[4];
    const float* W3    = (const float*)d_in[5];
    const float* b3    = (const float*)d_in[6];
    const float* sigma = (const float*)d_in[7];
    const float* gamma = (const float*)d_in[8];
    float* out = (float*)d_out;

    const int Brows = in_sizes[0] / 128;                     // 16384
    const int write_mu = (out_size >= Brows * 128) ? 1 : 0;  // tuple (weights, mu)

    prep_kernel<<<1, 64>>>(sigma);

    const int rows_per_block = 8;  // 4 warps x 2 rows
    const int grid = (Brows + rows_per_block - 1) / rows_per_block;
    fista_kernel<<<grid, 128>>>(x, W1, b1, W2, b2, W3, b3, sigma, gamma,
                                out, out + (size_t)Brows * 64, write_mu, Brows);
}

// round 17
// speedup vs baseline: 1.0941x; 1.0068x over previous
#include <cuda_runtime.h>
#include <cstdint>

#define FULLMASK 0xffffffffu

__device__ float g_step;
__device__ float g_beta[200];

// ---------------------------------------------------------------------------
// Prep kernel (1 block, 64 threads): lambda_max(sigma) via power iteration on
// S^4 (2 shared-memory squarings, 96 power steps, Rayleigh quotient, 4th
// root) -> g_step = 1/lambda_max. Thread 0 also precomputes the 200 FISTA
// momentum coefficients (fp32 recurrence identical to the reference).
// ---------------------------------------------------------------------------
__global__ void prep_kernel(const float* __restrict__ sigma) {
    __shared__ float A[64 * 64];
    __shared__ float Tm[64 * 64];
    __shared__ float v[64];
    __shared__ float red[64];
    const int t = threadIdx.x;

    for (int idx = t; idx < 4096; idx += 64) A[idx] = sigma[idx];
    __syncthreads();

    for (int i = 0; i < 64; ++i) {
        float acc = 0.f;
        for (int k = 0; k < 64; ++k) acc = fmaf(A[i * 64 + k], A[k * 64 + t], acc);
        Tm[i * 64 + t] = acc;
    }
    __syncthreads();
    for (int i = 0; i < 64; ++i) {
        float acc = 0.f;
        for (int k = 0; k < 64; ++k) acc = fmaf(Tm[i * 64 + k], Tm[k * 64 + t], acc);
        A[i * 64 + t] = acc;
    }
    __syncthreads();

    v[t] = 1.f + 0.01f * (float)t;
    __syncthreads();

    for (int it = 0; it < 96; ++it) {
        float acc = 0.f;
        for (int i = 0; i < 64; ++i) acc = fmaf(A[i * 64 + t], v[i], acc);
        __syncthreads();
        if ((it & 1) == 1) {
            red[t] = acc * acc;
            __syncthreads();
            for (int s = 32; s > 0; s >>= 1) {
                if (t < s) red[t] += red[t + s];
                __syncthreads();
            }
            acc *= rsqrtf(red[0]);
            __syncthreads();
        }
        v[t] = acc;
        __syncthreads();
    }

    float acc = 0.f;
    for (int i = 0; i < 64; ++i) acc = fmaf(A[i * 64 + t], v[i], acc);
    red[t] = acc * v[t];
    __syncthreads();
    for (int s = 32; s > 0; s >>= 1) {
        if (t < s) red[t] += red[t + s];
        __syncthreads();
    }
    float num = red[0];
    __syncthreads();
    red[t] = v[t] * v[t];
    __syncthreads();
    for (int s = 32; s > 0; s >>= 1) {
        if (t < s) red[t] += red[t + s];
        __syncthreads();
    }
    float den = red[0];

    if (t == 0) {
        float lam = sqrtf(sqrtf(num / den));
        g_step = 1.0f / lam;
        float tt = 1.f;
        for (int k = 0; k < 200; ++k) {
            float tn = 0.5f * (1.f + sqrtf(1.f + 4.f * tt * tt));
            g_beta[k] = (tt - 1.f) / tn;
            tt = tn;
        }
    }
}

// ---------------------------------------------------------------------------
// Main kernel: one warp solves TWO rows. M = I - step*Sigma lives in SHARED
// memory (16KB, shared by all 4 warps of the block) as packed f32x2 pairs
// (M[i][l], M[i][l+32]); y broadcasts are packed so both rows come from one
// LDS.128. Inner step: 1 LDS.128 + 1 LDS.64 + 2 fma.rn.f32x2 for 2 rows.
// Projection: Michelot active-set (exact). Early exit on bitwise-stationary
// state (provably identical output to running all 200 iterations).
// ---------------------------------------------------------------------------
__global__ void __launch_bounds__(128, 5) fista_kernel(
    const float* __restrict__ x,
    const float* __restrict__ W1, const float* __restrict__ b1,
    const float* __restrict__ W2, const float* __restrict__ b2,
    const float* __restrict__ W3, const float* __restrict__ b3,
    const float* __restrict__ sigma, const float* __restrict__ gammap,
    float* __restrict__ outw, float* __restrict__ outmu,
    int write_mu, int Brows)
{
    __shared__ unsigned long long Msh[64][32];     // 16 KB, block-shared
    __shared__ ulonglong2 ysh[4][2][64];           // 8 KB: [warp][buf][i] = {yA_i pair, yB_i pair}
    __shared__ float bsh[200];

    const int tid = threadIdx.x;
    const int wp = tid >> 5;
    const int l = tid & 31;

    const float step = g_step;

    // Block-cooperative: M = I - step*Sigma, packed pairs in shared
    for (int i = wp; i < 64; i += 4) {
        float a = ((i == l) ? 1.f : 0.f) - step * sigma[i * 64 + l];
        float b = ((i == l + 32) ? 1.f : 0.f) - step * sigma[i * 64 + l + 32];
        unsigned long long m;
        asm("mov.b64 %0, {%1, %2};" : "=l"(m) : "f"(a), "f"(b));
        Msh[i][l] = m;
    }
    for (int k = tid; k < 200; k += 128) bsh[k] = g_beta[k];
    __syncthreads();

    const int rowA = (blockIdx.x * 4 + wp) * 2;
    if (rowA >= Brows) return;
    const bool haveB = (rowA + 1) < Brows;
    const int rowB = haveB ? (rowA + 1) : rowA;
    const float gm = gammap[0];

    // ---- MLP prologue: mu = relu(relu(x@W1+b1)@W2+b2)@W3+b3, two rows ----
    float mu0[2], mu1[2];
#pragma unroll
    for (int r = 0; r < 2; ++r) {
        const float* xr = x + (size_t)(r == 0 ? rowA : rowB) * 128;
        float xa = xr[l], xb = xr[l + 32], xc = xr[l + 64], xd = xr[l + 96];
        float h1 = b1[l];
#pragma unroll
        for (int i = 0; i < 32; ++i) h1 = fmaf(__shfl_sync(FULLMASK, xa, i), W1[i * 32 + l], h1);
#pragma unroll
        for (int i = 0; i < 32; ++i) h1 = fmaf(__shfl_sync(FULLMASK, xb, i), W1[(i + 32) * 32 + l], h1);
#pragma unroll
        for (int i = 0; i < 32; ++i) h1 = fmaf(__shfl_sync(FULLMASK, xc, i), W1[(i + 64) * 32 + l], h1);
#pragma unroll
        for (int i = 0; i < 32; ++i) h1 = fmaf(__shfl_sync(FULLMASK, xd, i), W1[(i + 96) * 32 + l], h1);
        h1 = fmaxf(h1, 0.f);

        const int l16 = l & 15;
        float h2 = b2[l16];
#pragma unroll
        for (int i = 0; i < 32; ++i) h2 = fmaf(__shfl_sync(FULLMASK, h1, i), W2[i * 16 + l16], h2);
        h2 = fmaxf(h2, 0.f);

        float m0 = b3[l], m1 = b3[l + 32];
#pragma unroll
        for (int i = 0; i < 16; ++i) {
            float h2i = __shfl_sync(FULLMASK, h2, i);
            m0 = fmaf(h2i, W3[i * 64 + l], m0);
            m1 = fmaf(h2i, W3[i * 64 + l + 32], m1);
        }
        mu0[r] = m0; mu1[r] = m1;
    }

    if (write_mu) {
        outmu[(size_t)rowA * 64 + l] = mu0[0];
        outmu[(size_t)rowA * 64 + l + 32] = mu1[0];
        if (haveB) {
            outmu[(size_t)rowB * 64 + l] = mu0[1];
            outmu[(size_t)rowB * 64 + l + 32] = mu1[1];
        }
    }

    // q = step*gamma*mu, packed  (v = y@M + q == y - step*(y@Sigma + p))
    const float sg = step * gm;
    unsigned long long qA, qB;
    {
        float a = sg * mu0[0], b = sg * mu1[0];
        asm("mov.b64 %0, {%1, %2};" : "=l"(qA) : "f"(a), "f"(b));
        float c = sg * mu0[1], d = sg * mu1[1];
        asm("mov.b64 %0, {%1, %2};" : "=l"(qB) : "f"(c), "f"(d));
    }

    const float winit = 1.f / 64.f;
    float wA0 = winit, wA1 = winit, wB0 = winit, wB1 = winit;
    float yA0 = winit, yA1 = winit, yB0 = winit, yB1 = winit;

    for (int k = 0; k < 200; ++k) {
        const int buf = k & 1;
        // write y broadcasts: entry i holds {(yA_i,yA_i),(yB_i,yB_i)}
        {
            ulonglong2 e;
            asm("mov.b64 %0, {%1, %1};" : "=l"(e.x) : "f"(yA0));
            asm("mov.b64 %0, {%1, %1};" : "=l"(e.y) : "f"(yB0));
            ysh[wp][buf][l] = e;
            asm("mov.b64 %0, {%1, %1};" : "=l"(e.x) : "f"(yA1));
            asm("mov.b64 %0, {%1, %1};" : "=l"(e.y) : "f"(yB1));
            ysh[wp][buf][l + 32] = e;
        }
        __syncwarp();

        // v = y @ M + q : per i, 1 LDS.128 (both rows' y) + 1 LDS.64 (M) + 2 fma.f32x2
        unsigned long long vA0p = qA, vA1p = 0ull, vB0p = qB, vB1p = 0ull;
        const ulonglong2* Y = ysh[wp][buf];
#pragma unroll
        for (int i = 0; i < 64; i += 2) {
            ulonglong2 y0 = Y[i];
            ulonglong2 y1 = Y[i + 1];
            unsigned long long m0 = Msh[i][l];
            unsigned long long m1 = Msh[i + 1][l];
            asm("fma.rn.f32x2 %0, %1, %2, %0;" : "+l"(vA0p) : "l"(m0), "l"(y0.x));
            asm("fma.rn.f32x2 %0, %1, %2, %0;" : "+l"(vB0p) : "l"(m0), "l"(y0.y));
            asm("fma.rn.f32x2 %0, %1, %2, %0;" : "+l"(vA1p) : "l"(m1), "l"(y1.x));
            asm("fma.rn.f32x2 %0, %1, %2, %0;" : "+l"(vB1p) : "l"(m1), "l"(y1.y));
        }
        unsigned long long vA, vB;
        asm("add.rn.f32x2 %0, %1, %2;" : "=l"(vA) : "l"(vA0p), "l"(vA1p));
        asm("add.rn.f32x2 %0, %1, %2;" : "=l"(vB) : "l"(vB0p), "l"(vB1p));
        float vA0, vA1, vB0, vB1;
        asm("mov.b64 {%0, %1}, %2;" : "=f"(vA0), "=f"(vA1) : "l"(vA));
        asm("mov.b64 {%0, %1}, %2;" : "=f"(vB0), "=f"(vB1) : "l"(vB));

        // ---- simplex projection (Michelot, dual-row) ----
        float sA = vA0 + vA1, sB = vB0 + vB1;
#pragma unroll
        for (int o = 16; o > 0; o >>= 1) {
            sA += __shfl_xor_sync(FULLMASK, sA, o);
            sB += __shfl_xor_sync(FULLMASK, sB, o);
        }
        float thA = (sA - 1.f) * 0.015625f;
        float thB = (sB - 1.f) * 0.015625f;
        int cpA = 64, cpB = 64;
        bool dA = false, dB = false;
        for (int pass = 0; pass < 64; ++pass) {
            bool aA0 = vA0 > thA, aA1 = vA1 > thA;
            bool aB0 = vB0 > thB, aB1 = vB1 > thB;
            int cA = __popc(__ballot_sync(FULLMASK, aA0)) + __popc(__ballot_sync(FULLMASK, aA1));
            int cB = __popc(__ballot_sync(FULLMASK, aB0)) + __popc(__ballot_sync(FULLMASK, aB1));
            float slA = (aA0 ? vA0 : 0.f) + (aA1 ? vA1 : 0.f);
            float slB = (aB0 ? vB0 : 0.f) + (aB1 ? vB1 : 0.f);
#pragma unroll
            for (int o = 16; o > 0; o >>= 1) {
                slA += __shfl_xor_sync(FULLMASK, slA, o);
                slB += __shfl_xor_sync(FULLMASK, slB, o);
            }
            dA = dA || (cA == cpA);
            dB = dB || (cB == cpB);
            if (dA && dB) break;
            if (!dA) { thA = __fdividef(slA - 1.f, (float)cA); cpA = cA; }
            if (!dB) { thB = __fdividef(slB - 1.f, (float)cB); cpB = cB; }
        }
        float wnA0 = fmaxf(vA0 - thA, 0.f), wnA1 = fmaxf(vA1 - thA, 0.f);
        float wnB0 = fmaxf(vB0 - thB, 0.f), wnB1 = fmaxf(vB1 - thB, 0.f);

        // ---- momentum ----
        const float beta = bsh[k];
        float nyA0 = fmaf(beta, wnA0 - wA0, wnA0);
        float nyA1 = fmaf(beta, wnA1 - wA1, wnA1);
        float nyB0 = fmaf(beta, wnB0 - wB0, wnB0);
        float nyB1 = fmaf(beta, wnB1 - wB1, wnB1);

        // ---- exact early exit: state bitwise stationary => all remaining
        // iterations are identity (w_new==w forces y_new==w_new, beta-free) ----
        bool stA = (wnA0 == wA0) & (wnA1 == wA1) & (nyA0 == yA0) & (nyA1 == yA1);
        bool stB = (wnB0 == wB0) & (wnB1 == wB1) & (nyB0 == yB0) & (nyB1 == yB1);
        bool doneA = __all_sync(FULLMASK, stA);
        bool doneB = __all_sync(FULLMASK, stB);

        wA0 = wnA0; wA1 = wnA1; wB0 = wnB0; wB1 = wnB1;
        yA0 = nyA0; yA1 = nyA1; yB0 = nyB0; yB1 = nyB1;

        if (doneA && doneB) break;
    }

    outw[(size_t)rowA * 64 + l] = wA0;
    outw[(size_t)rowA * 64 + l + 32] = wA1;
    if (haveB) {
        outw[(size_t)rowB * 64 + l] = wB0;
        outw[(size_t)rowB * 64 + l + 32] = wB1;
    }
}

// ---------------------------------------------------------------------------
extern "C" void kernel_launch(void* const* d_in, const int* in_sizes, int n_in,
                              void* d_out, int out_size) {
    const float* x     = (const float*)d_in[0];
    const float* W1    = (const float*)d_in[1];
    const float* b1    = (const float*)d_in[2];
    const float* W2    = (const float*)d_in[3];
    const float* b2    = (const float*)d_in[4];
    const float* W3    = (const float*)d_in[5];
    const float* b3    = (const float*)d_in[6];
    const float* sigma = (const float*)d_in[7];
    const float* gamma = (const float*)d_in[8];
    float* out = (float*)d_out;

    const int Brows = in_sizes[0] / 128;                     // 16384
    const int write_mu = (out_size >= Brows * 128) ? 1 : 0;  // tuple (weights, mu)

    prep_kernel<<<1, 64>>>(sigma);

    const int rows_per_block = 8;  // 4 warps x 2 rows
    const int grid = (Brows + rows_per_block - 1) / rows_per_block;
    fista_kernel<<<grid, 128>>>(x, W1, b1, W2, b2, W3, b3, sigma, gamma,
                                out, out + (size_t)Brows * 64, write_mu, Brows);
}